// round 6
// baseline (speedup 1.0000x reference)
#include <cuda_runtime.h>
#include <cuda_fp16.h>
#include <cstdint>

// Fixed problem shapes
#define BB    16
#define DC    16
#define ND    1024
#define CIN   64
#define COUT  128
#define NN    4096
#define KW    7
#define NCH   8              // K chunks (8 channels each, 64 padded cols)

// Scratch (device globals; no allocation allowed)
__device__ float g_z[BB*CIN*ND];
__device__ float g_y[BB*CIN*NN];
__device__ float g_scale[BB*CIN];
__device__ float g_shift[BB*CIN];
__device__ __align__(16) __half g_wH[NCH*COUT*64];          // [ch][o][col]
__device__ __align__(16) __half g_m[(size_t)BB*NCH*NN*64];  // [b][ch][l][col]  64MB

#define CP16(dst, src) asm volatile("cp.async.cg.shared.global [%0], [%1], 16;" :: "r"(dst), "l"(src) : "memory")
#define CPCOMMIT()     asm volatile("cp.async.commit_group;" ::: "memory")
#define CPWAIT0()      asm volatile("cp.async.wait_group 0;" ::: "memory")
#define CPWAIT1()      asm volatile("cp.async.wait_group 1;" ::: "memory")

__device__ __forceinline__ uint32_t smem_u32(const void* p) {
    uint32_t a;
    asm("{ .reg .u64 t; cvta.to.shared.u64 t, %1; cvt.u32.u64 %0, t; }" : "=r"(a) : "l"(p));
    return a;
}
// pack(first, second) -> f16x2, first in bits[15:0]
__device__ __forceinline__ uint32_t packh(float a0, float a1) {
    uint32_t r;
    asm("cvt.rn.f16x2.f32 %0, %1, %2;" : "=r"(r) : "f"(a1), "f"(a0));
    return r;
}
#define LDSM4(r, a) \
    asm volatile("ldmatrix.sync.aligned.m8n8.x4.shared.b16 {%0,%1,%2,%3}, [%4];" \
        : "=r"((r)[0]), "=r"((r)[1]), "=r"((r)[2]), "=r"((r)[3]) : "r"(a))
#define MMAH(d, a, b0, b1) \
    asm volatile("mma.sync.aligned.m16n8k16.row.col.f32.f16.f16.f32 " \
        "{%0,%1,%2,%3},{%4,%5,%6,%7},{%8,%9},{%0,%1,%2,%3};" \
        : "+f"((d)[0]), "+f"((d)[1]), "+f"((d)[2]), "+f"((d)[3]) \
        : "r"((a)[0]), "r"((a)[1]), "r"((a)[2]), "r"((a)[3]), "r"(b0), "r"(b1))

// ---------------- kernel 1: z[b,c,m] = sum_d conv_w[c,d]*deep[b,d,m] ----------------
__global__ void k_z(const float* __restrict__ deep, const float* __restrict__ conv_w) {
    int idx = blockIdx.x * blockDim.x + threadIdx.x;
    if (idx >= BB*CIN*ND) return;
    int m = idx & (ND-1);
    int c = (idx >> 10) & (CIN-1);
    int b = idx >> 16;
    const float* dp = deep + (size_t)b*DC*ND + m;
    float acc = 0.f;
    #pragma unroll
    for (int d = 0; d < DC; ++d)
        acc += __ldg(&conv_w[c*DC + d]) * dp[(size_t)d*ND];
    g_z[idx] = acc;
}

// ---------------- kernel 2: fc_w -> fp16 chunk tiles ----------------
__global__ void k_wsplit(const float* __restrict__ fc_w) {
    int idx = blockIdx.x * blockDim.x + threadIdx.x;
    if (idx >= NCH*COUT*64) return;
    int ch  = idx >> 13;
    int o   = (idx >> 6) & 127;
    int col = idx & 63;
    int cc = col >> 3, k = col & 7;
    float v = 0.f;
    if (k < KW) v = fc_w[o*(CIN*KW) + (ch*8 + cc)*KW + k];
    g_wH[idx] = __float2half_rn(v);
}

// ---------------- kernel 3: y = lerp(z)+bias, per-(b,c) scale/shift ----------------
__global__ void k_stats(const float* __restrict__ conv_b) {
    __shared__ float sz[ND];
    __shared__ float red1[8], red2[8];
    int bc  = blockIdx.x;
    int c   = bc & (CIN-1);
    int tid = threadIdx.x;
    const float* zrow = g_z + (size_t)bc*ND;
    for (int i = tid; i < ND; i += 256) sz[i] = zrow[i];
    __syncthreads();
    float bias = conv_b[c];
    float s1 = 0.f, s2 = 0.f;
    float* yrow = g_y + (size_t)bc*NN;
    for (int n = tid; n < NN; n += 256) {
        float src = 0.25f*(float)n - 0.375f;
        src = fminf(fmaxf(src, 0.f), (float)(ND-1));
        int lo = (int)src;
        int hi = min(lo + 1, ND-1);
        float w = src - (float)lo;
        float v = sz[lo]*(1.f - w) + sz[hi]*w + bias;
        yrow[n] = v;
        s1 += v; s2 += v*v;
    }
    #pragma unroll
    for (int off = 16; off; off >>= 1) {
        s1 += __shfl_down_sync(0xffffffffu, s1, off);
        s2 += __shfl_down_sync(0xffffffffu, s2, off);
    }
    if ((tid & 31) == 0) { red1[tid>>5] = s1; red2[tid>>5] = s2; }
    __syncthreads();
    if (tid == 0) {
        float t1 = 0.f, t2 = 0.f;
        #pragma unroll
        for (int i = 0; i < 8; ++i) { t1 += red1[i]; t2 += red2[i]; }
        float mean = t1 / (float)NN;
        float var  = (t2 - (float)NN*mean*mean) / (float)(NN-1);
        float sc   = 0.5f / (var + 1e-9f);
        g_scale[bc] = sc;
        g_shift[bc] = -sc * mean;
    }
}

// ---------------- kernel 4: build m[b][ch][l][64] in fp16 ----------------
// grid (8 lblocks, 8 ch, 16 b), 256 threads, no inter-warp deps after one sync.
#define LB 512
__global__ __launch_bounds__(256)
void k_build(const float* __restrict__ x) {
    __shared__ float sx [8][LB+8];
    __shared__ float sxs[8][LB+8];
    const int lb = blockIdx.x, ch = blockIdx.y, b = blockIdx.z;
    const int tid = threadIdx.x;
    const int l0 = lb * LB;

    for (int t = tid; t < 8*(LB+6); t += 256) {
        int cc = t / (LB+6), i = t - cc*(LB+6);
        int p = l0 - 3 + i;
        if (p < 0)   p = -p;
        if (p >= NN) p = 2*NN - 2 - p;
        int bc = b*CIN + ch*8 + cc;
        sx [cc][i] = x[(size_t)bc*NN + p];
        sxs[cc][i] = g_scale[bc] * g_y[(size_t)bc*NN + p] + g_shift[bc];
    }
    __syncthreads();

    #pragma unroll
    for (int r = 0; r < 2; ++r) {
        const int ll = tid + r*256;                       // 0..511
        __half* rowp = g_m + ((size_t)(b*NCH + ch)*NN + l0 + ll)*64;
        #pragma unroll 2
        for (int cc = 0; cc < 8; ++cc) {
            const float* xsp = &sxs[cc][ll];
            const float* xp  = &sx [cc][ll];
            float ctr = xsp[3];
            float u[KW], q[KW];
            #pragma unroll
            for (int k = 0; k < KW; ++k) {
                u[k] = (k == 3) ? 1.0f : __expf(-2.0f * fabsf(xsp[k] - ctr));
                float v = 1.0f + u[k];
                q[k] = v * v;
            }
            float P[KW], S[KW];
            P[0] = 1.f;
            #pragma unroll
            for (int k = 1; k < KW; ++k) P[k] = P[k-1] * q[k-1];
            S[KW-1] = 1.f;
            #pragma unroll
            for (int k = KW-2; k >= 0; --k) S[k] = S[k+1] * q[k+1];
            float nmr[KW], den = 0.f;
            #pragma unroll
            for (int k = 0; k < KW; ++k) { nmr[k] = u[k] * P[k] * S[k]; den += nmr[k]; }
            float inv = __fdividef(1.0f, den);
            float m[8];
            #pragma unroll
            for (int k = 0; k < KW; ++k) m[k] = xp[k] * nmr[k] * inv;
            m[7] = 0.f;
            uint32_t h[4];
            #pragma unroll
            for (int j = 0; j < 4; ++j) h[j] = packh(m[2*j], m[2*j+1]);
            *(uint4*)(rowp + cc*8) = make_uint4(h[0], h[1], h[2], h[3]);
        }
    }
}

// ---------------- kernel 5: multistage cp.async HMMA GEMM ----------------
// grid (32 l-tiles, 16 b), 256 threads, 3 stages, 2 CTAs/SM.
// D[o(128) x l(128)] = sum_ch W[ch]·m[ch]^T
#define GROWB  144
#define GST_W  0
#define GST_M  (128*GROWB)            // 18432
#define GSTAGE (2*128*GROWB)          // 36864
#define GSMEM  (3*GSTAGE)             // 110592

__global__ __launch_bounds__(256, 2)
void k_gemm(float* __restrict__ out) {
    extern __shared__ __align__(16) char smem[];
    const uint32_t sb = smem_u32(smem);
    const int tid  = threadIdx.x;
    const int lane = tid & 31;
    const int wid  = tid >> 5;
    const int b    = blockIdx.y;
    const int l0   = blockIdx.x * 128;

    auto load_chunk = [&](int ch, int s) {
        const uint32_t st = sb + (uint32_t)(s * GSTAGE);
        const char* srcW = (const char*)(g_wH + (size_t)ch*COUT*64);
        const char* srcM = (const char*)(g_m + ((size_t)(b*NCH + ch)*NN + l0)*64);
        #pragma unroll
        for (int j = 0; j < 4; ++j) {
            int idx = tid + j*256;              // 0..1023
            int row = idx >> 3, seg = idx & 7;
            uint32_t d = (uint32_t)(row*GROWB + seg*16);
            CP16(st + GST_W + d, srcW + (size_t)idx*16);
            CP16(st + GST_M + d, srcM + (size_t)idx*16);
        }
        CPCOMMIT();
    };

    load_chunk(0, 0);
    load_chunk(1, 1);

    const int m0 = (wid & 1) * 64;      // o offset
    const int n0 = (wid >> 1) * 32;     // l offset
    const uint32_t laneA = (uint32_t)((lane & 15)*GROWB + ((lane >> 4) & 1)*16);
    const uint32_t laneB = (uint32_t)(((lane & 7) + 8*((lane >> 4) & 1))*GROWB + ((lane >> 3) & 1)*16);

    float acc[4][4][4];
    #pragma unroll
    for (int i = 0; i < 4; ++i)
        #pragma unroll
        for (int n = 0; n < 4; ++n)
            #pragma unroll
            for (int r = 0; r < 4; ++r) acc[i][n][r] = 0.f;

    #pragma unroll 1
    for (int ch = 0; ch < NCH; ++ch) {
        if (ch == NCH-1) { CPWAIT0(); } else { CPWAIT1(); }
        __syncthreads();
        if (ch + 2 < NCH) load_chunk(ch + 2, (ch + 2) % 3);

        const uint32_t sc = sb + (uint32_t)((ch % 3) * GSTAGE);
        #pragma unroll
        for (int ks = 0; ks < 4; ++ks) {
            const uint32_t kb = (uint32_t)(ks * 32);
            uint32_t a[4][4], bm[2][4];
            const uint32_t aW = sc + GST_W + (uint32_t)m0*GROWB + kb + laneA;
            const uint32_t bM = sc + GST_M + (uint32_t)n0*GROWB + kb + laneB;
            #pragma unroll
            for (int i = 0; i < 4; ++i)
                LDSM4(a[i], aW + i*16*GROWB);
            LDSM4(bm[0], bM);
            LDSM4(bm[1], bM + 16*GROWB);
            #pragma unroll
            for (int i = 0; i < 4; ++i) {
                #pragma unroll
                for (int n = 0; n < 4; ++n) {
                    const int jj = n >> 1, e = (n & 1)*2;
                    MMAH(acc[i][n], a[i], bm[jj][e], bm[jj][e+1]);
                }
            }
        }
    }

    // ---- epilogue: direct STG.64 ----
    const int g = lane >> 2, tq = lane & 3;
    float* outb = out + (size_t)b*COUT*NN + l0;
    #pragma unroll
    for (int i = 0; i < 4; ++i) {
        int o = m0 + i*16 + g;
        #pragma unroll
        for (int n = 0; n < 4; ++n) {
            int lp = n0 + n*8 + 2*tq;
            *(float2*)(outb + (size_t)o*NN + lp)     = make_float2(acc[i][n][0], acc[i][n][1]);
            *(float2*)(outb + (size_t)(o+8)*NN + lp) = make_float2(acc[i][n][2], acc[i][n][3]);
        }
    }
}

// ---------------- launch ----------------
extern "C" void kernel_launch(void* const* d_in, const int* in_sizes, int n_in,
                              void* d_out, int out_size) {
    const float* deep   = (const float*)d_in[0];
    const float* x      = (const float*)d_in[1];
    const float* conv_w = (const float*)d_in[2];
    const float* conv_b = (const float*)d_in[3];
    const float* fc_w   = (const float*)d_in[4];
    float* out = (float*)d_out;

    cudaFuncSetAttribute(k_gemm, cudaFuncAttributeMaxDynamicSharedMemorySize, GSMEM);

    k_wsplit<<<(NCH*COUT*64 + 255)/256, 256>>>(fc_w);
    k_z     <<<(BB*CIN*ND + 255)/256, 256>>>(deep, conv_w);
    k_stats <<<BB*CIN, 256>>>(conv_b);
    k_build <<<dim3(NN/LB, NCH, BB), 256>>>(x);
    k_gemm  <<<dim3(NN/128, BB), 256, GSMEM>>>(out);
}

// round 7
// speedup vs baseline: 1.6814x; 1.6814x over previous
#include <cuda_runtime.h>
#include <cuda_fp16.h>
#include <cstdint>

// Fixed problem shapes
#define BB    16
#define DC    16
#define ND    1024
#define CIN   64
#define COUT  128
#define NN    4096
#define KW    7
#define LT    64             // l-tile per CTA
#define NCH   8              // K chunks (8 channels each)
#define NTHR  256            // 8 warps, all do build + MMA

// Scratch (device globals; no allocation allowed)
__device__ float g_z[BB*CIN*ND];
__device__ float g_y[BB*CIN*NN];
__device__ float g_scale[BB*CIN];
__device__ float g_shift[BB*CIN];
__device__ __align__(16) __half g_wH[NCH*COUT*64];   // [ch][o][col], col=cc*8+k

// ---------------- smem layout (bytes) ----------------
#define ROWB   144                    // 64 fp16 cols padded to 72 -> conflict-free ldmatrix
#define OFF_X    0                    // 64 ch x 72 floats = 18432
#define OFF_XS   18432                // 18432
#define OFF_ST   36864
#define T_W      0                    // 128 o rows x 144B = 18432
#define T_M      18432                // 64 l rows x 144B  = 9216
#define STAGE_BYTES 27648
#define SMEM_TOTAL (OFF_ST + 2*STAGE_BYTES)   // 92160 -> 2 CTAs/SM

#define CP16(dst, src) asm volatile("cp.async.cg.shared.global [%0], [%1], 16;" :: "r"(dst), "l"(src) : "memory")
#define CPCOMMIT()     asm volatile("cp.async.commit_group;" ::: "memory")
#define CPWAIT0()      asm volatile("cp.async.wait_group 0;" ::: "memory")

__device__ __forceinline__ uint32_t smem_u32(const void* p) {
    uint32_t a;
    asm("{ .reg .u64 t; cvta.to.shared.u64 t, %1; cvt.u32.u64 %0, t; }" : "=r"(a) : "l"(p));
    return a;
}
// pack(first, second) -> f16x2, first in bits[15:0]
__device__ __forceinline__ uint32_t packh(float a0, float a1) {
    uint32_t r;
    asm("cvt.rn.f16x2.f32 %0, %1, %2;" : "=r"(r) : "f"(a1), "f"(a0));
    return r;
}
#define LDSM4(r, a) \
    asm volatile("ldmatrix.sync.aligned.m8n8.x4.shared.b16 {%0,%1,%2,%3}, [%4];" \
        : "=r"((r)[0]), "=r"((r)[1]), "=r"((r)[2]), "=r"((r)[3]) : "r"(a))
#define MMAH(d, a, b0, b1) \
    asm volatile("mma.sync.aligned.m16n8k16.row.col.f32.f16.f16.f32 " \
        "{%0,%1,%2,%3},{%4,%5,%6,%7},{%8,%9},{%0,%1,%2,%3};" \
        : "+f"((d)[0]), "+f"((d)[1]), "+f"((d)[2]), "+f"((d)[3]) \
        : "r"((a)[0]), "r"((a)[1]), "r"((a)[2]), "r"((a)[3]), "r"(b0), "r"(b1))

// ---------------- kernel 1: z[b,c,m] = sum_d conv_w[c,d]*deep[b,d,m] ----------------
__global__ void k_z(const float* __restrict__ deep, const float* __restrict__ conv_w) {
    int idx = blockIdx.x * blockDim.x + threadIdx.x;
    if (idx >= BB*CIN*ND) return;
    int m = idx & (ND-1);
    int c = (idx >> 10) & (CIN-1);
    int b = idx >> 16;
    const float* dp = deep + (size_t)b*DC*ND + m;
    float acc = 0.f;
    #pragma unroll
    for (int d = 0; d < DC; ++d)
        acc += __ldg(&conv_w[c*DC + d]) * dp[(size_t)d*ND];
    g_z[idx] = acc;
}

// ---------------- kernel 2: fc_w -> fp16 chunk tiles ----------------
__global__ void k_wsplit(const float* __restrict__ fc_w) {
    int idx = blockIdx.x * blockDim.x + threadIdx.x;
    if (idx >= NCH*COUT*64) return;
    int ch  = idx >> 13;
    int o   = (idx >> 6) & 127;
    int col = idx & 63;
    int cc = col >> 3, k = col & 7;
    float v = 0.f;
    if (k < KW) v = fc_w[o*(CIN*KW) + (ch*8 + cc)*KW + k];
    g_wH[idx] = __float2half_rn(v);
}

// ---------------- kernel 3: y = lerp(z)+bias, per-(b,c) scale/shift ----------------
__global__ void k_stats(const float* __restrict__ conv_b) {
    __shared__ float sz[ND];
    __shared__ float red1[8], red2[8];
    int bc  = blockIdx.x;
    int c   = bc & (CIN-1);
    int tid = threadIdx.x;
    const float* zrow = g_z + (size_t)bc*ND;
    for (int i = tid; i < ND; i += 256) sz[i] = zrow[i];
    __syncthreads();
    float bias = conv_b[c];
    float s1 = 0.f, s2 = 0.f;
    float* yrow = g_y + (size_t)bc*NN;
    for (int n = tid; n < NN; n += 256) {
        float src = 0.25f*(float)n - 0.375f;
        src = fminf(fmaxf(src, 0.f), (float)(ND-1));
        int lo = (int)src;
        int hi = min(lo + 1, ND-1);
        float w = src - (float)lo;
        float v = sz[lo]*(1.f - w) + sz[hi]*w + bias;
        yrow[n] = v;
        s1 += v; s2 += v*v;
    }
    #pragma unroll
    for (int off = 16; off; off >>= 1) {
        s1 += __shfl_down_sync(0xffffffffu, s1, off);
        s2 += __shfl_down_sync(0xffffffffu, s2, off);
    }
    if ((tid & 31) == 0) { red1[tid>>5] = s1; red2[tid>>5] = s2; }
    __syncthreads();
    if (tid == 0) {
        float t1 = 0.f, t2 = 0.f;
        #pragma unroll
        for (int i = 0; i < 8; ++i) { t1 += red1[i]; t2 += red2[i]; }
        float mean = t1 / (float)NN;
        float var  = (t2 - (float)NN*mean*mean) / (float)(NN-1);
        float sc   = 0.5f / (var + 1e-9f);
        g_scale[bc] = sc;
        g_shift[bc] = -sc * mean;
    }
}

// ---------------- build one chunk's m tile (all warps) ----------------
__device__ __forceinline__ void build_m(char* stage, int ch, int tid,
                                        const float* smx, const float* smxs) {
    #pragma unroll
    for (int t2 = 0; t2 < 2; ++t2) {
        int t  = tid + t2*NTHR;          // 0..511
        int l  = t & 63;
        int cc = t >> 6;
        int c  = ch*8 + cc;
        const float* xsp = smxs + c*72 + l;
        const float* xp  = smx  + c*72 + l;
        float ctr = xsp[3];
        float u[KW], q[KW];
        #pragma unroll
        for (int k = 0; k < KW; ++k) {
            u[k] = (k == 3) ? 1.0f : __expf(-2.0f * fabsf(xsp[k] - ctr));
            float v = 1.0f + u[k];
            q[k] = v * v;
        }
        float P[KW], S[KW];
        P[0] = 1.f;
        #pragma unroll
        for (int k = 1; k < KW; ++k) P[k] = P[k-1] * q[k-1];
        S[KW-1] = 1.f;
        #pragma unroll
        for (int k = KW-2; k >= 0; --k) S[k] = S[k+1] * q[k+1];
        float nmr[KW], den = 0.f;
        #pragma unroll
        for (int k = 0; k < KW; ++k) { nmr[k] = u[k] * P[k] * S[k]; den += nmr[k]; }
        float inv = __fdividef(1.0f, den);
        float m[8];
        #pragma unroll
        for (int k = 0; k < KW; ++k) m[k] = xp[k] * nmr[k] * inv;
        m[7] = 0.f;
        uint32_t h[4];
        #pragma unroll
        for (int j = 0; j < 4; ++j) h[j] = packh(m[2*j], m[2*j+1]);
        *(uint4*)(stage + T_M + l*ROWB + cc*16) = make_uint4(h[0], h[1], h[2], h[3]);
    }
}

__device__ __forceinline__ void load_w(uint32_t st, int ch, int tid) {
    const char* src = (const char*)(g_wH + (size_t)ch*COUT*64);
    #pragma unroll
    for (int j = 0; j < 4; ++j) {
        int idx = tid + j*NTHR;          // 0..1023
        int o = idx >> 3, seg = idx & 7;
        CP16(st + T_W + (uint32_t)(o*ROWB + seg*16), src + (size_t)idx*16);
    }
    CPCOMMIT();
}

// ---------------- kernel 4: all-hands fused build + HMMA GEMM ----------------
// grid (NN/LT=64, BB=16) = 1024 CTAs, 256 threads, 2 CTAs/SM.
// D[o(128) x l(64)] = sum_f W[o,f]*m[l,f], fp16 single pass.
__global__ __launch_bounds__(NTHR, 2)
void k_tc(const float* __restrict__ x, float* __restrict__ out) {
    extern __shared__ __align__(16) char smem[];
    const uint32_t sb = smem_u32(smem);
    const int tid  = threadIdx.x;
    const int lane = tid & 31;
    const int wid  = tid >> 5;
    const int b    = blockIdx.y;
    const int l0   = blockIdx.x * LT;

    // ---- persistent x/xs staging: 64 channels x 70 positions (halo 3) ----
    float* smx  = (float*)(smem + OFF_X);
    float* smxs = (float*)(smem + OFF_XS);
    for (int t = tid; t < CIN*70; t += NTHR) {
        int c = t / 70, i = t - c*70;
        int p = l0 - 3 + i;
        if (p < 0)   p = -p;
        if (p >= NN) p = 2*NN - 2 - p;
        int bc = b*CIN + c;
        smx [c*72 + i] = x[(size_t)bc*NN + p];
        smxs[c*72 + i] = g_scale[bc] * g_y[(size_t)bc*NN + p] + g_shift[bc];
    }
    load_w(sb + OFF_ST, 0, tid);        // W0 -> stage 0 (async)
    __syncthreads();

    build_m(smem + OFF_ST, 0, tid, smx, smxs);
    CPWAIT0();
    __syncthreads();                    // stage 0 ready

    const int m0 = (wid & 3) * 32;      // o offset (4 warps across o)
    const int n0 = (wid >> 2) * 32;     // l offset (2 warps across l)
    const uint32_t laneA = (uint32_t)((lane & 15)*ROWB + ((lane >> 4) & 1)*16);
    const uint32_t laneB = (uint32_t)(((lane & 7) + 8*((lane >> 4) & 1))*ROWB + ((lane >> 3) & 1)*16);

    float acc[2][4][4];
    #pragma unroll
    for (int i = 0; i < 2; ++i)
        #pragma unroll
        for (int n = 0; n < 4; ++n)
            #pragma unroll
            for (int r = 0; r < 4; ++r) acc[i][n][r] = 0.f;

    #pragma unroll 1
    for (int ch = 0; ch < NCH; ++ch) {
        const int s = ch & 1;
        const uint32_t stc = sb + (uint32_t)(OFF_ST + s*STAGE_BYTES);
        // produce next stage first (independent work, fills MMA stall slots)
        if (ch + 1 < NCH) {
            const uint32_t stn = sb + (uint32_t)(OFF_ST + (s^1)*STAGE_BYTES);
            load_w(stn, ch + 1, tid);
            build_m(smem + OFF_ST + (s^1)*STAGE_BYTES, ch + 1, tid, smx, smxs);
        }
        // MMA on current stage
        #pragma unroll
        for (int ks = 0; ks < 4; ++ks) {
            const uint32_t kb = (uint32_t)(ks * 32);
            uint32_t a[2][4], bm[2][4];
            const uint32_t aW = stc + T_W + (uint32_t)m0*ROWB + kb + laneA;
            const uint32_t bM = stc + T_M + (uint32_t)n0*ROWB + kb + laneB;
            LDSM4(a[0], aW);
            LDSM4(a[1], aW + 16*ROWB);
            LDSM4(bm[0], bM);
            LDSM4(bm[1], bM + 16*ROWB);
            #pragma unroll
            for (int i = 0; i < 2; ++i) {
                #pragma unroll
                for (int n = 0; n < 4; ++n) {
                    const int jj = n >> 1, e = (n & 1)*2;
                    MMAH(acc[i][n], a[i], bm[jj][e], bm[jj][e+1]);
                }
            }
        }
        if (ch + 1 < NCH) CPWAIT0();
        __syncthreads();
    }

    // ---- epilogue: direct STG.64 ----
    const int g = lane >> 2, tq = lane & 3;
    float* outb = out + (size_t)b*COUT*NN + l0;
    #pragma unroll
    for (int i = 0; i < 2; ++i) {
        int o = m0 + i*16 + g;
        #pragma unroll
        for (int n = 0; n < 4; ++n) {
            int lp = n0 + n*8 + 2*tq;
            *(float2*)(outb + (size_t)o*NN + lp)     = make_float2(acc[i][n][0], acc[i][n][1]);
            *(float2*)(outb + (size_t)(o+8)*NN + lp) = make_float2(acc[i][n][2], acc[i][n][3]);
        }
    }
}

// ---------------- launch ----------------
extern "C" void kernel_launch(void* const* d_in, const int* in_sizes, int n_in,
                              void* d_out, int out_size) {
    const float* deep   = (const float*)d_in[0];
    const float* x      = (const float*)d_in[1];
    const float* conv_w = (const float*)d_in[2];
    const float* conv_b = (const float*)d_in[3];
    const float* fc_w   = (const float*)d_in[4];
    float* out = (float*)d_out;

    cudaFuncSetAttribute(k_tc, cudaFuncAttributeMaxDynamicSharedMemorySize, SMEM_TOTAL);

    k_wsplit<<<(NCH*COUT*64 + 255)/256, 256>>>(fc_w);
    k_z     <<<(BB*CIN*ND + 255)/256, 256>>>(deep, conv_w);
    k_stats <<<BB*CIN, 256>>>(conv_b);
    k_tc    <<<dim3(NN/LT, BB), NTHR, SMEM_TOTAL>>>(x, out);
}

// round 8
// speedup vs baseline: 1.8264x; 1.0862x over previous
#include <cuda_runtime.h>
#include <cuda_fp16.h>
#include <cstdint>

// Fixed problem shapes
#define BB    16
#define DC    16
#define ND    1024
#define CIN   64
#define COUT  128
#define NN    4096
#define KW    7
#define LT    64             // l-tile per CTA
#define NCH   8              // K chunks (8 channels each)
#define NTHR  512            // 16 warps, all do build + MMA

// Scratch (device globals; no allocation allowed)
__device__ float g_z[BB*CIN*ND];
__device__ float g_y[BB*CIN*NN];
__device__ float g_scale[BB*CIN];
__device__ float g_shift[BB*CIN];
__device__ __align__(16) __half g_wH[NCH*COUT*64];   // [ch][o][col], col=cc*8+k

// ---------------- smem layout (bytes) ----------------
#define ROWB   144                    // 64 fp16 cols padded to 72 -> conflict-free ldmatrix
#define OFF_X    0                    // 64 ch x 72 floats = 18432
#define OFF_XS   18432                // 18432
#define OFF_ST   36864
#define T_W      0                    // 128 o rows x 144B = 18432
#define T_M      18432                // 64 l rows x 144B  = 9216
#define STAGE_BYTES 27648
#define SMEM_TOTAL (OFF_ST + 2*STAGE_BYTES)   // 92160 -> 2 CTAs/SM

#define CP16(dst, src) asm volatile("cp.async.cg.shared.global [%0], [%1], 16;" :: "r"(dst), "l"(src) : "memory")
#define CPCOMMIT()     asm volatile("cp.async.commit_group;" ::: "memory")
#define CPWAIT0()      asm volatile("cp.async.wait_group 0;" ::: "memory")

__device__ __forceinline__ uint32_t smem_u32(const void* p) {
    uint32_t a;
    asm("{ .reg .u64 t; cvta.to.shared.u64 t, %1; cvt.u32.u64 %0, t; }" : "=r"(a) : "l"(p));
    return a;
}
// pack(first, second) -> f16x2, first in bits[15:0]
__device__ __forceinline__ uint32_t packh(float a0, float a1) {
    uint32_t r;
    asm("cvt.rn.f16x2.f32 %0, %1, %2;" : "=r"(r) : "f"(a1), "f"(a0));
    return r;
}
#define LDSM4(r, a) \
    asm volatile("ldmatrix.sync.aligned.m8n8.x4.shared.b16 {%0,%1,%2,%3}, [%4];" \
        : "=r"((r)[0]), "=r"((r)[1]), "=r"((r)[2]), "=r"((r)[3]) : "r"(a))
#define MMAH(d, a, b0, b1) \
    asm volatile("mma.sync.aligned.m16n8k16.row.col.f32.f16.f16.f32 " \
        "{%0,%1,%2,%3},{%4,%5,%6,%7},{%8,%9},{%0,%1,%2,%3};" \
        : "+f"((d)[0]), "+f"((d)[1]), "+f"((d)[2]), "+f"((d)[3]) \
        : "r"((a)[0]), "r"((a)[1]), "r"((a)[2]), "r"((a)[3]), "r"(b0), "r"(b1))

// ---------------- kernel 1: z[b,c,m] = sum_d conv_w[c,d]*deep[b,d,m] ----------------
__global__ void k_z(const float* __restrict__ deep, const float* __restrict__ conv_w) {
    int idx = blockIdx.x * blockDim.x + threadIdx.x;
    if (idx >= BB*CIN*ND) return;
    int m = idx & (ND-1);
    int c = (idx >> 10) & (CIN-1);
    int b = idx >> 16;
    const float* dp = deep + (size_t)b*DC*ND + m;
    float acc = 0.f;
    #pragma unroll
    for (int d = 0; d < DC; ++d)
        acc += __ldg(&conv_w[c*DC + d]) * dp[(size_t)d*ND];
    g_z[idx] = acc;
}

// ---------------- kernel 2: fc_w -> fp16 chunk tiles ----------------
__global__ void k_wsplit(const float* __restrict__ fc_w) {
    int idx = blockIdx.x * blockDim.x + threadIdx.x;
    if (idx >= NCH*COUT*64) return;
    int ch  = idx >> 13;
    int o   = (idx >> 6) & 127;
    int col = idx & 63;
    int cc = col >> 3, k = col & 7;
    float v = 0.f;
    if (k < KW) v = fc_w[o*(CIN*KW) + (ch*8 + cc)*KW + k];
    g_wH[idx] = __float2half_rn(v);
}

// ---------------- kernel 3: y = lerp(z)+bias, per-(b,c) scale/shift ----------------
__global__ void k_stats(const float* __restrict__ conv_b) {
    __shared__ float sz[ND];
    __shared__ float red1[8], red2[8];
    int bc  = blockIdx.x;
    int c   = bc & (CIN-1);
    int tid = threadIdx.x;
    const float* zrow = g_z + (size_t)bc*ND;
    for (int i = tid; i < ND; i += 256) sz[i] = zrow[i];
    __syncthreads();
    float bias = conv_b[c];
    float s1 = 0.f, s2 = 0.f;
    float* yrow = g_y + (size_t)bc*NN;
    for (int n = tid; n < NN; n += 256) {
        float src = 0.25f*(float)n - 0.375f;
        src = fminf(fmaxf(src, 0.f), (float)(ND-1));
        int lo = (int)src;
        int hi = min(lo + 1, ND-1);
        float w = src - (float)lo;
        float v = sz[lo]*(1.f - w) + sz[hi]*w + bias;
        yrow[n] = v;
        s1 += v; s2 += v*v;
    }
    #pragma unroll
    for (int off = 16; off; off >>= 1) {
        s1 += __shfl_down_sync(0xffffffffu, s1, off);
        s2 += __shfl_down_sync(0xffffffffu, s2, off);
    }
    if ((tid & 31) == 0) { red1[tid>>5] = s1; red2[tid>>5] = s2; }
    __syncthreads();
    if (tid == 0) {
        float t1 = 0.f, t2 = 0.f;
        #pragma unroll
        for (int i = 0; i < 8; ++i) { t1 += red1[i]; t2 += red2[i]; }
        float mean = t1 / (float)NN;
        float var  = (t2 - (float)NN*mean*mean) / (float)(NN-1);
        float sc   = 0.5f / (var + 1e-9f);
        g_scale[bc] = sc;
        g_shift[bc] = -sc * mean;
    }
}

// ---------------- build one chunk's m tile: ONE task per thread ----------------
__device__ __forceinline__ void build_m(char* stage, int ch, int tid,
                                        const float* smx, const float* smxs) {
    int l  = tid & 63;
    int cc = tid >> 6;                  // 0..7
    int c  = ch*8 + cc;
    const float* xsp = smxs + c*72 + l;
    const float* xp  = smx  + c*72 + l;
    float ctr = xsp[3];
    float s[KW];
    float den;
    // direct per-tap sech^2 with rcp: small register footprint
    #pragma unroll
    for (int k = 0; k < KW; ++k) {
        if (k == 3) { s[k] = 1.0f; }
        else {
            float u = __expf(-2.0f * fabsf(xsp[k] - ctr));
            float v = 1.0f + u;
            s[k] = __fdividef(4.0f * u, v * v);
        }
    }
    den = s[0] + s[1] + s[2] + s[3] + s[4] + s[5] + s[6];
    float inv = __frcp_rn(den);
    float m[8];
    #pragma unroll
    for (int k = 0; k < KW; ++k) m[k] = xp[k] * s[k] * inv;
    m[7] = 0.f;
    uint32_t h[4];
    #pragma unroll
    for (int j = 0; j < 4; ++j) h[j] = packh(m[2*j], m[2*j+1]);
    *(uint4*)(stage + T_M + l*ROWB + cc*16) = make_uint4(h[0], h[1], h[2], h[3]);
}

__device__ __forceinline__ void load_w(uint32_t st, int ch, int tid) {
    const char* src = (const char*)(g_wH + (size_t)ch*COUT*64);
    #pragma unroll
    for (int j = 0; j < 2; ++j) {
        int idx = tid + j*NTHR;          // 0..1023
        int o = idx >> 3, seg = idx & 7;
        CP16(st + T_W + (uint32_t)(o*ROWB + seg*16), src + (size_t)idx*16);
    }
    CPCOMMIT();
}

// ---------------- kernel 4: all-hands fused build + HMMA GEMM ----------------
// grid (NN/LT=64, BB=16) = 1024 CTAs, 512 threads, 2 CTAs/SM (32 warps/SM).
// D[o(128) x l(64)] = sum_f W[o,f]*m[l,f], fp16 single pass.
__global__ __launch_bounds__(NTHR, 2)
void k_tc(const float* __restrict__ x, float* __restrict__ out) {
    extern __shared__ __align__(16) char smem[];
    const uint32_t sb = smem_u32(smem);
    const int tid  = threadIdx.x;
    const int lane = tid & 31;
    const int wid  = tid >> 5;
    const int b    = blockIdx.y;
    const int l0   = blockIdx.x * LT;

    // ---- persistent x/xs staging: 64 channels x 70 positions (halo 3) ----
    float* smx  = (float*)(smem + OFF_X);
    float* smxs = (float*)(smem + OFF_XS);
    for (int t = tid; t < CIN*70; t += NTHR) {
        int c = t / 70, i = t - c*70;
        int p = l0 - 3 + i;
        if (p < 0)   p = -p;
        if (p >= NN) p = 2*NN - 2 - p;
        int bc = b*CIN + c;
        smx [c*72 + i] = x[(size_t)bc*NN + p];
        smxs[c*72 + i] = g_scale[bc] * g_y[(size_t)bc*NN + p] + g_shift[bc];
    }
    load_w(sb + OFF_ST, 0, tid);        // W0 -> stage 0 (async)
    __syncthreads();

    build_m(smem + OFF_ST, 0, tid, smx, smxs);
    CPWAIT0();
    __syncthreads();                    // stage 0 ready

    const int m0 = (wid & 3) * 32;      // o offset (4 warps across o)
    const int n0 = (wid >> 2) * 16;     // l offset (4 warps across l)
    const uint32_t laneA = (uint32_t)((lane & 15)*ROWB + ((lane >> 4) & 1)*16);
    const uint32_t laneB = (uint32_t)(((lane & 7) + 8*((lane >> 4) & 1))*ROWB + ((lane >> 3) & 1)*16);

    float acc[2][2][4];
    #pragma unroll
    for (int i = 0; i < 2; ++i)
        #pragma unroll
        for (int n = 0; n < 2; ++n)
            #pragma unroll
            for (int r = 0; r < 4; ++r) acc[i][n][r] = 0.f;

    #pragma unroll 1
    for (int ch = 0; ch < NCH; ++ch) {
        const int s = ch & 1;
        const uint32_t stc = sb + (uint32_t)(OFF_ST + s*STAGE_BYTES);
        // produce next stage first (independent work, fills MMA stall slots)
        if (ch + 1 < NCH) {
            const uint32_t stn = sb + (uint32_t)(OFF_ST + (s^1)*STAGE_BYTES);
            load_w(stn, ch + 1, tid);
            build_m(smem + OFF_ST + (s^1)*STAGE_BYTES, ch + 1, tid, smx, smxs);
        }
        // MMA on current stage
        #pragma unroll
        for (int ks = 0; ks < 4; ++ks) {
            const uint32_t kb = (uint32_t)(ks * 32);
            uint32_t a[2][4], bm[4];
            const uint32_t aW = stc + T_W + (uint32_t)m0*ROWB + kb + laneA;
            const uint32_t bM = stc + T_M + (uint32_t)n0*ROWB + kb + laneB;
            LDSM4(a[0], aW);
            LDSM4(a[1], aW + 16*ROWB);
            LDSM4(bm, bM);
            #pragma unroll
            for (int i = 0; i < 2; ++i) {
                #pragma unroll
                for (int n = 0; n < 2; ++n) {
                    const int e = n*2;
                    MMAH(acc[i][n], a[i], bm[e], bm[e+1]);
                }
            }
        }
        if (ch + 1 < NCH) CPWAIT0();
        __syncthreads();
    }

    // ---- epilogue: direct STG.64 ----
    const int g = lane >> 2, tq = lane & 3;
    float* outb = out + (size_t)b*COUT*NN + l0;
    #pragma unroll
    for (int i = 0; i < 2; ++i) {
        int o = m0 + i*16 + g;
        #pragma unroll
        for (int n = 0; n < 2; ++n) {
            int lp = n0 + n*8 + 2*tq;
            *(float2*)(outb + (size_t)o*NN + lp)     = make_float2(acc[i][n][0], acc[i][n][1]);
            *(float2*)(outb + (size_t)(o+8)*NN + lp) = make_float2(acc[i][n][2], acc[i][n][3]);
        }
    }
}

// ---------------- launch ----------------
extern "C" void kernel_launch(void* const* d_in, const int* in_sizes, int n_in,
                              void* d_out, int out_size) {
    const float* deep   = (const float*)d_in[0];
    const float* x      = (const float*)d_in[1];
    const float* conv_w = (const float*)d_in[2];
    const float* conv_b = (const float*)d_in[3];
    const float* fc_w   = (const float*)d_in[4];
    float* out = (float*)d_out;

    cudaFuncSetAttribute(k_tc, cudaFuncAttributeMaxDynamicSharedMemorySize, SMEM_TOTAL);

    k_wsplit<<<(NCH*COUT*64 + 255)/256, 256>>>(fc_w);
    k_z     <<<(BB*CIN*ND + 255)/256, 256>>>(deep, conv_w);
    k_stats <<<BB*CIN, 256>>>(conv_b);
    k_tc    <<<dim3(NN/LT, BB), NTHR, SMEM_TOTAL>>>(x, out);
}

// round 9
// speedup vs baseline: 1.8599x; 1.0184x over previous
#include <cuda_runtime.h>
#include <cuda_fp16.h>
#include <cstdint>

// Fixed problem shapes
#define BB    16
#define DC    16
#define ND    1024
#define CIN   64
#define COUT  128
#define NN    4096
#define KW    7
#define LT    64             // l-tile per CTA
#define NCH   8              // K chunks (8 channels each)
#define NTHR  512            // 16 warps, all do build + MMA

// Scratch (device globals; no allocation allowed)
__device__ float g_z[BB*CIN*ND];
__device__ float g_scale[BB*CIN];
__device__ float g_shift[BB*CIN];
__device__ __align__(16) __half g_wH[NCH*COUT*64];   // [ch][o][col], col=cc*8+k

// ---------------- smem layout (bytes) ----------------
#define ROWB   144                    // 64 fp16 cols padded to 72 -> conflict-free ldmatrix
#define OFF_XY   0                    // 64 ch x 72 float2 = 36864  (x, xs interleaved)
#define OFF_ST   36864
#define T_W      0                    // 128 o rows x 144B = 18432
#define T_M      18432                // 64 l rows x 144B  = 9216
#define STAGE_BYTES 27648
#define SMEM_TOTAL (OFF_ST + 2*STAGE_BYTES)   // 92160 -> 2 CTAs/SM

#define CP16(dst, src) asm volatile("cp.async.cg.shared.global [%0], [%1], 16;" :: "r"(dst), "l"(src) : "memory")
#define CPCOMMIT()     asm volatile("cp.async.commit_group;" ::: "memory")
#define CPWAIT0()      asm volatile("cp.async.wait_group 0;" ::: "memory")

__device__ __forceinline__ uint32_t smem_u32(const void* p) {
    uint32_t a;
    asm("{ .reg .u64 t; cvta.to.shared.u64 t, %1; cvt.u32.u64 %0, t; }" : "=r"(a) : "l"(p));
    return a;
}
__device__ __forceinline__ float rcpa(float x) {
    float r;
    asm("rcp.approx.f32 %0, %1;" : "=f"(r) : "f"(x));
    return r;
}
// pack(first, second) -> f16x2, first in bits[15:0]
__device__ __forceinline__ uint32_t packh(float a0, float a1) {
    uint32_t r;
    asm("cvt.rn.f16x2.f32 %0, %1, %2;" : "=r"(r) : "f"(a1), "f"(a0));
    return r;
}
#define LDSM4(r, a) \
    asm volatile("ldmatrix.sync.aligned.m8n8.x4.shared.b16 {%0,%1,%2,%3}, [%4];" \
        : "=r"((r)[0]), "=r"((r)[1]), "=r"((r)[2]), "=r"((r)[3]) : "r"(a))
#define MMAH(d, a, b0, b1) \
    asm volatile("mma.sync.aligned.m16n8k16.row.col.f32.f16.f16.f32 " \
        "{%0,%1,%2,%3},{%4,%5,%6,%7},{%8,%9},{%0,%1,%2,%3};" \
        : "+f"((d)[0]), "+f"((d)[1]), "+f"((d)[2]), "+f"((d)[3]) \
        : "r"((a)[0]), "r"((a)[1]), "r"((a)[2]), "r"((a)[3]), "r"(b0), "r"(b1))

// ---------------- kernel 1: fc_w -> fp16 chunk tiles ----------------
__global__ void k_wsplit(const float* __restrict__ fc_w) {
    int idx = blockIdx.x * blockDim.x + threadIdx.x;
    if (idx >= NCH*COUT*64) return;
    int ch  = idx >> 13;
    int o   = (idx >> 6) & 127;
    int col = idx & 63;
    int cc = col >> 3, k = col & 7;
    float v = 0.f;
    if (k < KW) v = fc_w[o*(CIN*KW) + (ch*8 + cc)*KW + k];
    g_wH[idx] = __float2half_rn(v);
}

// ---------------- kernel 2: fused z + stats (no g_y) ----------------
// block per (b,c): compute z row in smem, write g_z, stats of y = lerp(z)+bias.
__global__ void k_prep(const float* __restrict__ deep, const float* __restrict__ conv_w,
                       const float* __restrict__ conv_b) {
    __shared__ float sz[ND];
    __shared__ float cw[DC];
    __shared__ float red1[8], red2[8];
    int bc  = blockIdx.x;
    int c   = bc & (CIN-1);
    int b   = bc >> 6;
    int tid = threadIdx.x;
    if (tid < DC) cw[tid] = conv_w[c*DC + tid];
    __syncthreads();
    const float* dp = deep + (size_t)b*DC*ND;
    float* zrow = g_z + (size_t)bc*ND;
    for (int m = tid; m < ND; m += 256) {
        float acc = 0.f;
        #pragma unroll
        for (int d = 0; d < DC; ++d) acc += cw[d] * dp[(size_t)d*ND + m];
        sz[m] = acc;
        zrow[m] = acc;
    }
    __syncthreads();
    float bias = conv_b[c];
    float s1 = 0.f, s2 = 0.f;
    for (int n = tid; n < NN; n += 256) {
        float src = 0.25f*(float)n - 0.375f;
        src = fminf(fmaxf(src, 0.f), (float)(ND-1));
        int lo = (int)src;
        int hi = min(lo + 1, ND-1);
        float w = src - (float)lo;
        float v = sz[lo]*(1.f - w) + sz[hi]*w + bias;
        s1 += v; s2 += v*v;
    }
    #pragma unroll
    for (int off = 16; off; off >>= 1) {
        s1 += __shfl_down_sync(0xffffffffu, s1, off);
        s2 += __shfl_down_sync(0xffffffffu, s2, off);
    }
    if ((tid & 31) == 0) { red1[tid>>5] = s1; red2[tid>>5] = s2; }
    __syncthreads();
    if (tid == 0) {
        float t1 = 0.f, t2 = 0.f;
        #pragma unroll
        for (int i = 0; i < 8; ++i) { t1 += red1[i]; t2 += red2[i]; }
        float mean = t1 / (float)NN;
        float var  = (t2 - (float)NN*mean*mean) / (float)(NN-1);
        float sc   = 0.5f / (var + 1e-9f);
        g_scale[bc] = sc;
        g_shift[bc] = -sc * mean;
    }
}

// ---------------- build one chunk's m tile: ONE task per thread ----------------
__device__ __forceinline__ void build_m(char* stage, int ch, int tid, const float2* sxy) {
    int l  = tid & 63;
    int cc = tid >> 6;                  // 0..7
    const float2* tp = sxy + (ch*8 + cc)*72 + l;
    float2 t0 = tp[0], t1 = tp[1], t2 = tp[2], t3 = tp[3], t4 = tp[4], t5 = tp[5], t6 = tp[6];
    float ctr = t3.y;
    // r_k = u/(1+u)^2 (factor 4 cancels in normalization); tap3: r = 1/4
    #define RTAP(t) ({ float u_ = __expf(-2.0f*fabsf((t).y - ctr)); float v_ = 1.0f + u_; u_ * rcpa(v_*v_); })
    float r0 = RTAP(t0), r1 = RTAP(t1), r2 = RTAP(t2);
    float r4 = RTAP(t4), r5 = RTAP(t5), r6 = RTAP(t6);
    #undef RTAP
    float den = ((r0 + r1) + (r2 + 0.25f)) + ((r4 + r5) + r6);
    float inv = rcpa(den);
    float m0 = t0.x * (r0 * inv);
    float m1 = t1.x * (r1 * inv);
    float m2 = t2.x * (r2 * inv);
    float m3 = t3.x * (0.25f * inv);
    float m4 = t4.x * (r4 * inv);
    float m5 = t5.x * (r5 * inv);
    float m6 = t6.x * (r6 * inv);
    uint32_t h0 = packh(m0, m1), h1 = packh(m2, m3), h2 = packh(m4, m5), h3 = packh(m6, 0.f);
    *(uint4*)(stage + T_M + l*ROWB + cc*16) = make_uint4(h0, h1, h2, h3);
}

__device__ __forceinline__ void load_w(uint32_t st, int ch, int tid) {
    const char* src = (const char*)(g_wH + (size_t)ch*COUT*64);
    #pragma unroll
    for (int j = 0; j < 2; ++j) {
        int idx = tid + j*NTHR;          // 0..1023
        int o = idx >> 3, seg = idx & 7;
        CP16(st + T_W + (uint32_t)(o*ROWB + seg*16), src + (size_t)idx*16);
    }
    CPCOMMIT();
}

// ---------------- kernel 3: all-hands fused build + HMMA GEMM ----------------
// grid (NN/LT=64, BB=16) = 1024 CTAs, 512 threads, 2 CTAs/SM (32 warps/SM).
// D[o(128) x l(64)] = sum_f W[o,f]*m[l,f], fp16 single pass.
__global__ __launch_bounds__(NTHR, 2)
void k_tc(const float* __restrict__ x, const float* __restrict__ conv_b,
          float* __restrict__ out) {
    extern __shared__ __align__(16) char smem[];
    const uint32_t sb = smem_u32(smem);
    const int tid  = threadIdx.x;
    const int lane = tid & 31;
    const int wid  = tid >> 5;
    const int b    = blockIdx.y;
    const int l0   = blockIdx.x * LT;

    // ---- staging: (x, xs) float2 pairs, 64 channels x 70 positions (halo 3) ----
    float2* sxy = (float2*)(smem + OFF_XY);
    load_w(sb + OFF_ST, 0, tid);        // W0 -> stage 0 (async)
    for (int t = tid; t < CIN*70; t += NTHR) {
        int c = t / 70, i = t - c*70;
        int p = l0 - 3 + i;
        if (p < 0)   p = -p;
        if (p >= NN) p = 2*NN - 2 - p;
        int bc = b*CIN + c;
        // y = lerp(z) + bias (recomputed from g_z; identical fp ops to k_prep)
        float src = 0.25f*(float)p - 0.375f;
        src = fminf(fmaxf(src, 0.f), (float)(ND-1));
        int lo = (int)src;
        int hi = min(lo + 1, ND-1);
        float w = src - (float)lo;
        const float* zrow = g_z + (size_t)bc*ND;
        float v = zrow[lo]*(1.f - w) + zrow[hi]*w + conv_b[c];
        sxy[c*72 + i] = make_float2(x[(size_t)bc*NN + p],
                                    g_scale[bc] * v + g_shift[bc]);
    }
    __syncthreads();

    build_m(smem + OFF_ST, 0, tid, sxy);
    CPWAIT0();
    __syncthreads();                    // stage 0 ready

    const int m0 = (wid & 3) * 32;      // o offset (4 warps across o)
    const int n0 = (wid >> 2) * 16;     // l offset (4 warps across l)
    const uint32_t laneA = (uint32_t)((lane & 15)*ROWB + ((lane >> 4) & 1)*16);
    const uint32_t laneB = (uint32_t)(((lane & 7) + 8*((lane >> 4) & 1))*ROWB + ((lane >> 3) & 1)*16);

    float acc[2][2][4];
    #pragma unroll
    for (int i = 0; i < 2; ++i)
        #pragma unroll
        for (int n = 0; n < 2; ++n)
            #pragma unroll
            for (int r = 0; r < 4; ++r) acc[i][n][r] = 0.f;

    #pragma unroll 1
    for (int ch = 0; ch < NCH; ++ch) {
        const int s = ch & 1;
        const uint32_t stc = sb + (uint32_t)(OFF_ST + s*STAGE_BYTES);
        // produce next stage first (independent work, fills MMA stall slots)
        if (ch + 1 < NCH) {
            const uint32_t stn = sb + (uint32_t)(OFF_ST + (s^1)*STAGE_BYTES);
            load_w(stn, ch + 1, tid);
            build_m(smem + OFF_ST + (s^1)*STAGE_BYTES, ch + 1, tid, sxy);
        }
        // MMA on current stage
        #pragma unroll
        for (int ks = 0; ks < 4; ++ks) {
            const uint32_t kb = (uint32_t)(ks * 32);
            uint32_t a[2][4], bm[4];
            const uint32_t aW = stc + T_W + (uint32_t)m0*ROWB + kb + laneA;
            const uint32_t bM = stc + T_M + (uint32_t)n0*ROWB + kb + laneB;
            LDSM4(a[0], aW);
            LDSM4(a[1], aW + 16*ROWB);
            LDSM4(bm, bM);
            #pragma unroll
            for (int i = 0; i < 2; ++i) {
                #pragma unroll
                for (int n = 0; n < 2; ++n) {
                    const int e = n*2;
                    MMAH(acc[i][n], a[i], bm[e], bm[e+1]);
                }
            }
        }
        if (ch + 1 < NCH) CPWAIT0();
        __syncthreads();
    }

    // ---- epilogue: direct STG.64 ----
    const int g = lane >> 2, tq = lane & 3;
    float* outb = out + (size_t)b*COUT*NN + l0;
    #pragma unroll
    for (int i = 0; i < 2; ++i) {
        int o = m0 + i*16 + g;
        #pragma unroll
        for (int n = 0; n < 2; ++n) {
            int lp = n0 + n*8 + 2*tq;
            *(float2*)(outb + (size_t)o*NN + lp)     = make_float2(acc[i][n][0], acc[i][n][1]);
            *(float2*)(outb + (size_t)(o+8)*NN + lp) = make_float2(acc[i][n][2], acc[i][n][3]);
        }
    }
}

// ---------------- launch ----------------
extern "C" void kernel_launch(void* const* d_in, const int* in_sizes, int n_in,
                              void* d_out, int out_size) {
    const float* deep   = (const float*)d_in[0];
    const float* x      = (const float*)d_in[1];
    const float* conv_w = (const float*)d_in[2];
    const float* conv_b = (const float*)d_in[3];
    const float* fc_w   = (const float*)d_in[4];
    float* out = (float*)d_out;

    cudaFuncSetAttribute(k_tc, cudaFuncAttributeMaxDynamicSharedMemorySize, SMEM_TOTAL);

    k_wsplit<<<(NCH*COUT*64 + 255)/256, 256>>>(fc_w);
    k_prep  <<<BB*CIN, 256>>>(deep, conv_w, conv_b);
    k_tc    <<<dim3(NN/LT, BB), NTHR, SMEM_TOTAL>>>(x, conv_b, out);
}

// round 10
// speedup vs baseline: 1.8780x; 1.0097x over previous
#include <cuda_runtime.h>
#include <cuda_fp16.h>
#include <cstdint>

// Fixed problem shapes
#define BB    16
#define DC    16
#define ND    1024
#define CIN   64
#define COUT  128
#define NN    4096
#define KW    7
#define LT    128            // l-tile per CTA
#define NCH   8              // K chunks (8 channels each)
#define NTHR  512            // 16 warps, warp tile 32o x 32l

// Scratch (device globals; no allocation allowed)
__device__ float g_z[BB*CIN*ND];
__device__ float g_scale[BB*CIN];
__device__ float g_shift[BB*CIN];
__device__ __align__(16) __half g_wH[NCH*COUT*64];   // [ch][o][col], col=cc*8+k

// ---------------- smem layout (bytes) ----------------
#define ROWB   144                    // 64 fp16 cols padded to 72 -> conflict-free ldmatrix
#define XYBUF_B  8704                 // 8 ch x 136 float2
#define OFF_XY   0                    // 2 buffers = 17408
#define OFF_ST   17408
#define T_W      0                    // 128 o rows x 144B = 18432
#define T_M      18432                // 128 l rows x 144B = 18432
#define STAGE_BYTES 36864
#define SMEM_TOTAL (OFF_ST + 2*STAGE_BYTES)   // 91136 -> 2 CTAs/SM

#define CP16(dst, src) asm volatile("cp.async.cg.shared.global [%0], [%1], 16;" :: "r"(dst), "l"(src) : "memory")
#define CPCOMMIT()     asm volatile("cp.async.commit_group;" ::: "memory")
#define CPWAIT0()      asm volatile("cp.async.wait_group 0;" ::: "memory")

__device__ __forceinline__ uint32_t smem_u32(const void* p) {
    uint32_t a;
    asm("{ .reg .u64 t; cvta.to.shared.u64 t, %1; cvt.u32.u64 %0, t; }" : "=r"(a) : "l"(p));
    return a;
}
__device__ __forceinline__ float rcpa(float x) {
    float r;
    asm("rcp.approx.f32 %0, %1;" : "=f"(r) : "f"(x));
    return r;
}
// pack(first, second) -> f16x2, first in bits[15:0]
__device__ __forceinline__ uint32_t packh(float a0, float a1) {
    uint32_t r;
    asm("cvt.rn.f16x2.f32 %0, %1, %2;" : "=r"(r) : "f"(a1), "f"(a0));
    return r;
}
#define LDSM4(r, a) \
    asm volatile("ldmatrix.sync.aligned.m8n8.x4.shared.b16 {%0,%1,%2,%3}, [%4];" \
        : "=r"((r)[0]), "=r"((r)[1]), "=r"((r)[2]), "=r"((r)[3]) : "r"(a))
#define MMAH(d, a, b0, b1) \
    asm volatile("mma.sync.aligned.m16n8k16.row.col.f32.f16.f16.f32 " \
        "{%0,%1,%2,%3},{%4,%5,%6,%7},{%8,%9},{%0,%1,%2,%3};" \
        : "+f"((d)[0]), "+f"((d)[1]), "+f"((d)[2]), "+f"((d)[3]) \
        : "r"((a)[0]), "r"((a)[1]), "r"((a)[2]), "r"((a)[3]), "r"(b0), "r"(b1))

// ---------------- kernel 1: fused z + stats + wsplit ----------------
// block per (b,c). Threads 0..63 also convert a 64-element slice of fc_w.
__global__ void k_prep(const float* __restrict__ deep, const float* __restrict__ conv_w,
                       const float* __restrict__ conv_b, const float* __restrict__ fc_w) {
    __shared__ float sz[ND];
    __shared__ float cw[DC];
    __shared__ float red1[8], red2[8];
    int bc  = blockIdx.x;
    int c   = bc & (CIN-1);
    int b   = bc >> 6;
    int tid = threadIdx.x;
    // fc_w -> fp16 chunk tiles (65536 elems over 1024 blocks)
    if (tid < 64) {
        int idx = bc*64 + tid;
        int ch  = idx >> 13;
        int o   = (idx >> 6) & 127;
        int col = idx & 63;
        int cc = col >> 3, k = col & 7;
        float v = (k < KW) ? fc_w[o*(CIN*KW) + (ch*8 + cc)*KW + k] : 0.f;
        g_wH[idx] = __float2half_rn(v);
    }
    if (tid < DC) cw[tid] = conv_w[c*DC + tid];
    __syncthreads();
    const float* dp = deep + (size_t)b*DC*ND;
    float* zrow = g_z + (size_t)bc*ND;
    for (int m = tid; m < ND; m += 256) {
        float acc = 0.f;
        #pragma unroll
        for (int d = 0; d < DC; ++d) acc += cw[d] * dp[(size_t)d*ND + m];
        sz[m] = acc;
        zrow[m] = acc;
    }
    __syncthreads();
    float bias = conv_b[c];
    float s1 = 0.f, s2 = 0.f;
    for (int n = tid; n < NN; n += 256) {
        float src = 0.25f*(float)n - 0.375f;
        src = fminf(fmaxf(src, 0.f), (float)(ND-1));
        int lo = (int)src;
        int hi = min(lo + 1, ND-1);
        float w = src - (float)lo;
        float v = sz[lo]*(1.f - w) + sz[hi]*w + bias;
        s1 += v; s2 += v*v;
    }
    #pragma unroll
    for (int off = 16; off; off >>= 1) {
        s1 += __shfl_down_sync(0xffffffffu, s1, off);
        s2 += __shfl_down_sync(0xffffffffu, s2, off);
    }
    if ((tid & 31) == 0) { red1[tid>>5] = s1; red2[tid>>5] = s2; }
    __syncthreads();
    if (tid == 0) {
        float t1 = 0.f, t2 = 0.f;
        #pragma unroll
        for (int i = 0; i < 8; ++i) { t1 += red1[i]; t2 += red2[i]; }
        float mean = t1 / (float)NN;
        float var  = (t2 - (float)NN*mean*mean) / (float)(NN-1);
        float sc   = 0.5f / (var + 1e-9f);
        g_scale[bc] = sc;
        g_shift[bc] = -sc * mean;
    }
}

// ---------------- per-chunk xy staging: 8 channels x 134 positions ----------------
__device__ __forceinline__ void xy_stage(float2* buf, int ch, int b, int l0, int tid,
                                         const float* __restrict__ x,
                                         const float* __restrict__ conv_b) {
    for (int t = tid; t < 8*134; t += NTHR) {
        int cc = t / 134, i = t - cc*134;
        int p = l0 - 3 + i;
        if (p < 0)   p = -p;
        if (p >= NN) p = 2*NN - 2 - p;
        int c  = ch*8 + cc;
        int bc = b*CIN + c;
        float src = 0.25f*(float)p - 0.375f;
        src = fminf(fmaxf(src, 0.f), (float)(ND-1));
        int lo = (int)src;
        int hi = min(lo + 1, ND-1);
        float w = src - (float)lo;
        const float* zrow = g_z + (size_t)bc*ND;
        float v = zrow[lo]*(1.f - w) + zrow[hi]*w + conv_b[c];
        buf[cc*136 + i] = make_float2(x[(size_t)bc*NN + p],
                                      g_scale[bc] * v + g_shift[bc]);
    }
}

// ---------------- build one chunk's m tile: TWO tasks per thread ----------------
__device__ __forceinline__ void build_m(char* stage, const float2* buf, int tid) {
    #pragma unroll
    for (int j = 0; j < 2; ++j) {
        int t  = tid + j*NTHR;           // 0..1023
        int l  = t & 127;
        int cc = t >> 7;
        const float2* tp = buf + cc*136 + l;
        float2 t0 = tp[0], t1 = tp[1], t2 = tp[2], t3 = tp[3], t4 = tp[4], t5 = tp[5], t6 = tp[6];
        float ctr = t3.y;
        #define RTAP(tt) ({ float u_ = __expf(-2.0f*fabsf((tt).y - ctr)); float v_ = 1.0f + u_; u_ * rcpa(v_*v_); })
        float r0 = RTAP(t0), r1 = RTAP(t1), r2 = RTAP(t2);
        float r4 = RTAP(t4), r5 = RTAP(t5), r6 = RTAP(t6);
        #undef RTAP
        float den = ((r0 + r1) + (r2 + 0.25f)) + ((r4 + r5) + r6);
        float inv = rcpa(den);
        float m0 = t0.x * (r0 * inv);
        float m1 = t1.x * (r1 * inv);
        float m2 = t2.x * (r2 * inv);
        float m3 = t3.x * (0.25f * inv);
        float m4 = t4.x * (r4 * inv);
        float m5 = t5.x * (r5 * inv);
        float m6 = t6.x * (r6 * inv);
        uint32_t h0 = packh(m0, m1), h1 = packh(m2, m3), h2 = packh(m4, m5), h3 = packh(m6, 0.f);
        *(uint4*)(stage + T_M + l*ROWB + cc*16) = make_uint4(h0, h1, h2, h3);
    }
}

__device__ __forceinline__ void load_w(uint32_t st, int ch, int tid) {
    const char* src = (const char*)(g_wH + (size_t)ch*COUT*64);
    for (int idx = tid; idx < 1024; idx += NTHR) {
        int o = idx >> 3, seg = idx & 7;
        CP16(st + T_W + (uint32_t)(o*ROWB + seg*16), src + (size_t)idx*16);
    }
    CPCOMMIT();
}

// ---------------- kernel 2: fused build + HMMA GEMM, 128x128 tile ----------------
// grid (NN/LT=32, BB=16) = 512 CTAs, 512 threads, 2 CTAs/SM (32 warps/SM).
// Warp tile 32o x 32l (4x4 grid). Per-chunk 8-channel xy staging, 2 ahead.
__global__ __launch_bounds__(NTHR, 2)
void k_tc(const float* __restrict__ x, const float* __restrict__ conv_b,
          float* __restrict__ out) {
    extern __shared__ __align__(16) char smem[];
    const uint32_t sb = smem_u32(smem);
    const int tid  = threadIdx.x;
    const int lane = tid & 31;
    const int wid  = tid >> 5;
    const int b    = blockIdx.y;
    const int l0   = blockIdx.x * LT;

    float2* xy0 = (float2*)(smem + OFF_XY);
    float2* xy1 = (float2*)(smem + OFF_XY + XYBUF_B);

    // ---- prologue ----
    load_w(sb + OFF_ST, 0, tid);                  // W0 -> stage0 (async)
    xy_stage(xy0, 0, b, l0, tid, x, conv_b);
    __syncthreads();                              // xy(0) visible
    xy_stage(xy1, 1, b, l0, tid, x, conv_b);
    build_m(smem + OFF_ST, xy0, tid);             // M(0) from xy(0)
    CPWAIT0();                                    // W0 landed
    __syncthreads();                              // stage0 + xy(1) ready

    const int m0 = (wid & 3) * 32;      // o offset (4 warps across o)
    const int n0 = (wid >> 2) * 32;     // l offset (4 warps across l)
    const uint32_t laneA = (uint32_t)((lane & 15)*ROWB + ((lane >> 4) & 1)*16);
    const uint32_t laneB = (uint32_t)(((lane & 7) + 8*((lane >> 4) & 1))*ROWB + ((lane >> 3) & 1)*16);

    float acc[2][4][4];
    #pragma unroll
    for (int i = 0; i < 2; ++i)
        #pragma unroll
        for (int n = 0; n < 4; ++n)
            #pragma unroll
            for (int r = 0; r < 4; ++r) acc[i][n][r] = 0.f;

    #pragma unroll 1
    for (int ch = 0; ch < NCH; ++ch) {
        const int s = ch & 1;
        const uint32_t stc = sb + (uint32_t)(OFF_ST + s*STAGE_BYTES);
        // stage two ahead / build one ahead (independent of MMA below)
        if (ch + 1 < NCH) load_w(sb + OFF_ST + (s^1)*STAGE_BYTES, ch + 1, tid);
        if (ch + 2 < NCH) xy_stage(s ? xy1 : xy0, ch + 2, b, l0, tid, x, conv_b);
        if (ch + 1 < NCH) build_m(smem + OFF_ST + (s^1)*STAGE_BYTES, s ? xy0 : xy1, tid);
        // MMA on current stage
        #pragma unroll
        for (int ks = 0; ks < 4; ++ks) {
            const uint32_t kb = (uint32_t)(ks * 32);
            uint32_t a[2][4], bm[2][4];
            const uint32_t aW = stc + T_W + (uint32_t)m0*ROWB + kb + laneA;
            const uint32_t bM = stc + T_M + (uint32_t)n0*ROWB + kb + laneB;
            LDSM4(a[0], aW);
            LDSM4(a[1], aW + 16*ROWB);
            LDSM4(bm[0], bM);
            LDSM4(bm[1], bM + 16*ROWB);
            #pragma unroll
            for (int i = 0; i < 2; ++i) {
                #pragma unroll
                for (int n = 0; n < 4; ++n) {
                    const int jj = n >> 1, e = (n & 1)*2;
                    MMAH(acc[i][n], a[i], bm[jj][e], bm[jj][e+1]);
                }
            }
        }
        if (ch + 1 < NCH) CPWAIT0();
        __syncthreads();
    }

    // ---- epilogue: direct STG.64 ----
    const int g = lane >> 2, tq = lane & 3;
    float* outb = out + (size_t)b*COUT*NN + l0;
    #pragma unroll
    for (int i = 0; i < 2; ++i) {
        int o = m0 + i*16 + g;
        #pragma unroll
        for (int n = 0; n < 4; ++n) {
            int lp = n0 + n*8 + 2*tq;
            *(float2*)(outb + (size_t)o*NN + lp)     = make_float2(acc[i][n][0], acc[i][n][1]);
            *(float2*)(outb + (size_t)(o+8)*NN + lp) = make_float2(acc[i][n][2], acc[i][n][3]);
        }
    }
}

// ---------------- launch ----------------
extern "C" void kernel_launch(void* const* d_in, const int* in_sizes, int n_in,
                              void* d_out, int out_size) {
    const float* deep   = (const float*)d_in[0];
    const float* x      = (const float*)d_in[1];
    const float* conv_w = (const float*)d_in[2];
    const float* conv_b = (const float*)d_in[3];
    const float* fc_w   = (const float*)d_in[4];
    float* out = (float*)d_out;

    cudaFuncSetAttribute(k_tc, cudaFuncAttributeMaxDynamicSharedMemorySize, SMEM_TOTAL);

    k_prep<<<BB*CIN, 256>>>(deep, conv_w, conv_b, fc_w);
    k_tc  <<<dim3(NN/LT, BB), NTHR, SMEM_TOTAL>>>(x, conv_b, out);
}

// round 11
// speedup vs baseline: 1.9747x; 1.0515x over previous
#include <cuda_runtime.h>
#include <cuda_fp16.h>
#include <cstdint>

// Fixed problem shapes
#define BB    16
#define DC    16
#define ND    1024
#define CIN   64
#define COUT  128
#define NN    4096
#define KW    7
#define LT    64             // l-tile per CTA
#define NCH   8              // K chunks (8 channels each)
#define NTHR  512            // 16 warps, all do build + MMA

// Scratch (device globals; no allocation allowed)
__device__ float g_z[BB*CIN*ND];
__device__ float g_scale[BB*CIN];
__device__ float g_shift[BB*CIN];
__device__ __align__(16) __half g_wH[NCH*COUT*64];   // [ch][o][col], col=cc*8+k

// ---------------- smem layout (bytes) ----------------
#define ROWB   144                    // 64 fp16 cols padded to 72 -> conflict-free ldmatrix
#define OFF_XY   0                    // 64 ch x 72 float2 = 36864  (x, xs interleaved)
#define OFF_ST   36864
#define T_W      0                    // 128 o rows x 144B = 18432
#define T_M      18432                // 64 l rows x 144B  = 9216
#define STAGE_BYTES 27648
#define SMEM_TOTAL (OFF_ST + 2*STAGE_BYTES)   // 92160 -> 2 CTAs/SM

#define CP16(dst, src) asm volatile("cp.async.cg.shared.global [%0], [%1], 16;" :: "r"(dst), "l"(src) : "memory")
#define CPCOMMIT()     asm volatile("cp.async.commit_group;" ::: "memory")
#define CPWAIT0()      asm volatile("cp.async.wait_group 0;" ::: "memory")

__device__ __forceinline__ uint32_t smem_u32(const void* p) {
    uint32_t a;
    asm("{ .reg .u64 t; cvta.to.shared.u64 t, %1; cvt.u32.u64 %0, t; }" : "=r"(a) : "l"(p));
    return a;
}
__device__ __forceinline__ float rcpa(float x) {
    float r;
    asm("rcp.approx.f32 %0, %1;" : "=f"(r) : "f"(x));
    return r;
}
// pack(first, second) -> f16x2, first in bits[15:0]
__device__ __forceinline__ uint32_t packh(float a0, float a1) {
    uint32_t r;
    asm("cvt.rn.f16x2.f32 %0, %1, %2;" : "=r"(r) : "f"(a1), "f"(a0));
    return r;
}
#define LDSM4(r, a) \
    asm volatile("ldmatrix.sync.aligned.m8n8.x4.shared.b16 {%0,%1,%2,%3}, [%4];" \
        : "=r"((r)[0]), "=r"((r)[1]), "=r"((r)[2]), "=r"((r)[3]) : "r"(a))
#define MMAH(d, a, b0, b1) \
    asm volatile("mma.sync.aligned.m16n8k16.row.col.f32.f16.f16.f32 " \
        "{%0,%1,%2,%3},{%4,%5,%6,%7},{%8,%9},{%0,%1,%2,%3};" \
        : "+f"((d)[0]), "+f"((d)[1]), "+f"((d)[2]), "+f"((d)[3]) \
        : "r"((a)[0]), "r"((a)[1]), "r"((a)[2]), "r"((a)[3]), "r"(b0), "r"(b1))

// ---------------- kernel 1: fused z + stats + wsplit ----------------
// block per (b,c). Threads 0..63 also convert a 64-element slice of fc_w.
__global__ void k_prep(const float* __restrict__ deep, const float* __restrict__ conv_w,
                       const float* __restrict__ conv_b, const float* __restrict__ fc_w) {
    __shared__ float sz[ND];
    __shared__ float cw[DC];
    __shared__ float red1[8], red2[8];
    int bc  = blockIdx.x;
    int c   = bc & (CIN-1);
    int b   = bc >> 6;
    int tid = threadIdx.x;
    // fc_w -> fp16 chunk tiles (65536 elems over 1024 blocks)
    if (tid < 64) {
        int idx = bc*64 + tid;
        int ch  = idx >> 13;
        int o   = (idx >> 6) & 127;
        int col = idx & 63;
        int cc = col >> 3, k = col & 7;
        float v = (k < KW) ? fc_w[o*(CIN*KW) + (ch*8 + cc)*KW + k] : 0.f;
        g_wH[idx] = __float2half_rn(v);
    }
    if (tid < DC) cw[tid] = conv_w[c*DC + tid];
    __syncthreads();
    const float* dp = deep + (size_t)b*DC*ND;
    float* zrow = g_z + (size_t)bc*ND;
    for (int m = tid; m < ND; m += 256) {
        float acc = 0.f;
        #pragma unroll
        for (int d = 0; d < DC; ++d) acc += cw[d] * dp[(size_t)d*ND + m];
        sz[m] = acc;
        zrow[m] = acc;
    }
    __syncthreads();
    float bias = conv_b[c];
    float s1 = 0.f, s2 = 0.f;
    for (int n = tid; n < NN; n += 256) {
        float src = 0.25f*(float)n - 0.375f;
        src = fminf(fmaxf(src, 0.f), (float)(ND-1));
        int lo = (int)src;
        int hi = min(lo + 1, ND-1);
        float w = src - (float)lo;
        float v = sz[lo]*(1.f - w) + sz[hi]*w + bias;
        s1 += v; s2 += v*v;
    }
    #pragma unroll
    for (int off = 16; off; off >>= 1) {
        s1 += __shfl_down_sync(0xffffffffu, s1, off);
        s2 += __shfl_down_sync(0xffffffffu, s2, off);
    }
    if ((tid & 31) == 0) { red1[tid>>5] = s1; red2[tid>>5] = s2; }
    __syncthreads();
    if (tid == 0) {
        float t1 = 0.f, t2 = 0.f;
        #pragma unroll
        for (int i = 0; i < 8; ++i) { t1 += red1[i]; t2 += red2[i]; }
        float mean = t1 / (float)NN;
        float var  = (t2 - (float)NN*mean*mean) / (float)(NN-1);
        float sc   = 0.5f / (var + 1e-9f);
        g_scale[bc] = sc;
        g_shift[bc] = -sc * mean;
    }
}

// ---------------- build one chunk's m tile: ONE task per thread ----------------
__device__ __forceinline__ void build_m(char* stage, int ch, int tid, const float2* sxy) {
    int l  = tid & 63;
    int cc = tid >> 6;                  // 0..7
    const float2* tp = sxy + (ch*8 + cc)*72 + l;
    float2 t0 = tp[0], t1 = tp[1], t2 = tp[2], t3 = tp[3], t4 = tp[4], t5 = tp[5], t6 = tp[6];
    float ctr = t3.y;
    // r_k = u/(1+u)^2 (factor 4 cancels in normalization); tap3: r = 1/4
    #define RTAP(t) ({ float u_ = __expf(-2.0f*fabsf((t).y - ctr)); float v_ = 1.0f + u_; u_ * rcpa(v_*v_); })
    float r0 = RTAP(t0), r1 = RTAP(t1), r2 = RTAP(t2);
    float r4 = RTAP(t4), r5 = RTAP(t5), r6 = RTAP(t6);
    #undef RTAP
    float den = ((r0 + r1) + (r2 + 0.25f)) + ((r4 + r5) + r6);
    float inv = rcpa(den);
    float m0 = t0.x * (r0 * inv);
    float m1 = t1.x * (r1 * inv);
    float m2 = t2.x * (r2 * inv);
    float m3 = t3.x * (0.25f * inv);
    float m4 = t4.x * (r4 * inv);
    float m5 = t5.x * (r5 * inv);
    float m6 = t6.x * (r6 * inv);
    uint32_t h0 = packh(m0, m1), h1 = packh(m2, m3), h2 = packh(m4, m5), h3 = packh(m6, 0.f);
    *(uint4*)(stage + T_M + l*ROWB + cc*16) = make_uint4(h0, h1, h2, h3);
}

__device__ __forceinline__ void load_w(uint32_t st, int ch, int tid) {
    const char* src = (const char*)(g_wH + (size_t)ch*COUT*64);
    #pragma unroll
    for (int j = 0; j < 2; ++j) {
        int idx = tid + j*NTHR;          // 0..1023
        int o = idx >> 3, seg = idx & 7;
        CP16(st + T_W + (uint32_t)(o*ROWB + seg*16), src + (size_t)idx*16);
    }
    CPCOMMIT();
}

// ---------------- kernel 2: all-hands fused build + HMMA GEMM ----------------
// grid (NN/LT=64, BB=16) = 1024 CTAs, 512 threads, 2 CTAs/SM (32 warps/SM).
// D[o(128) x l(64)] = sum_f W[o,f]*m[l,f], fp16 single pass.
__global__ __launch_bounds__(NTHR, 2)
void k_tc(const float* __restrict__ x, const float* __restrict__ conv_b,
          float* __restrict__ out) {
    extern __shared__ __align__(16) char smem[];
    const uint32_t sb = smem_u32(smem);
    const int tid  = threadIdx.x;
    const int lane = tid & 31;
    const int wid  = tid >> 5;
    const int b    = blockIdx.y;
    const int l0   = blockIdx.x * LT;

    // ---- persistent staging: (x, xs) float2 pairs, 64 channels x 70 positions ----
    float2* sxy = (float2*)(smem + OFF_XY);
    load_w(sb + OFF_ST, 0, tid);        // W0 -> stage 0 (async)
    #pragma unroll 2
    for (int t = tid; t < CIN*70; t += NTHR) {
        int c = t / 70, i = t - c*70;
        int p = l0 - 3 + i;
        if (p < 0)   p = -p;
        if (p >= NN) p = 2*NN - 2 - p;
        int bc = b*CIN + c;
        // y = lerp(z) + bias (recomputed from g_z; identical fp ops to k_prep)
        float src = 0.25f*(float)p - 0.375f;
        src = fminf(fmaxf(src, 0.f), (float)(ND-1));
        int lo = (int)src;
        int hi = min(lo + 1, ND-1);
        float w = src - (float)lo;
        const float* zrow = g_z + (size_t)bc*ND;
        float v = zrow[lo]*(1.f - w) + zrow[hi]*w + conv_b[c];
        sxy[c*72 + i] = make_float2(x[(size_t)bc*NN + p],
                                    g_scale[bc] * v + g_shift[bc]);
    }
    __syncthreads();

    build_m(smem + OFF_ST, 0, tid, sxy);
    CPWAIT0();
    __syncthreads();                    // stage 0 ready

    const int m0 = (wid & 3) * 32;      // o offset (4 warps across o)
    const int n0 = (wid >> 2) * 16;     // l offset (4 warps across l)
    const uint32_t laneA = (uint32_t)((lane & 15)*ROWB + ((lane >> 4) & 1)*16);
    const uint32_t laneB = (uint32_t)(((lane & 7) + 8*((lane >> 4) & 1))*ROWB + ((lane >> 3) & 1)*16);

    float acc[2][2][4];
    #pragma unroll
    for (int i = 0; i < 2; ++i)
        #pragma unroll
        for (int n = 0; n < 2; ++n)
            #pragma unroll
            for (int r = 0; r < 4; ++r) acc[i][n][r] = 0.f;

    #pragma unroll 1
    for (int ch = 0; ch < NCH; ++ch) {
        const int s = ch & 1;
        const uint32_t stc = sb + (uint32_t)(OFF_ST + s*STAGE_BYTES);
        // produce next stage first (independent work, fills MMA stall slots)
        if (ch + 1 < NCH) {
            load_w(sb + (uint32_t)(OFF_ST + (s^1)*STAGE_BYTES), ch + 1, tid);
            build_m(smem + OFF_ST + (s^1)*STAGE_BYTES, ch + 1, tid, sxy);
        }
        // MMA on current stage
        const uint32_t aW0 = stc + T_W + (uint32_t)m0*ROWB + laneA;
        const uint32_t bM0 = stc + T_M + (uint32_t)n0*ROWB + laneB;
        #pragma unroll
        for (int ks = 0; ks < 4; ++ks) {
            const uint32_t kb = (uint32_t)(ks * 32);
            uint32_t a[2][4], bm[4];
            LDSM4(a[0], aW0 + kb);
            LDSM4(a[1], aW0 + kb + 16*ROWB);
            LDSM4(bm, bM0 + kb);
            #pragma unroll
            for (int i = 0; i < 2; ++i) {
                #pragma unroll
                for (int n = 0; n < 2; ++n) {
                    const int e = n*2;
                    MMAH(acc[i][n], a[i], bm[e], bm[e+1]);
                }
            }
        }
        if (ch + 1 < NCH) CPWAIT0();
        __syncthreads();
    }

    // ---- epilogue: direct STG.64 ----
    const int g = lane >> 2, tq = lane & 3;
    float* outb = out + (size_t)b*COUT*NN + l0;
    #pragma unroll
    for (int i = 0; i < 2; ++i) {
        int o = m0 + i*16 + g;
        #pragma unroll
        for (int n = 0; n < 2; ++n) {
            int lp = n0 + n*8 + 2*tq;
            *(float2*)(outb + (size_t)o*NN + lp)     = make_float2(acc[i][n][0], acc[i][n][1]);
            *(float2*)(outb + (size_t)(o+8)*NN + lp) = make_float2(acc[i][n][2], acc[i][n][3]);
        }
    }
}

// ---------------- launch ----------------
extern "C" void kernel_launch(void* const* d_in, const int* in_sizes, int n_in,
                              void* d_out, int out_size) {
    const float* deep   = (const float*)d_in[0];
    const float* x      = (const float*)d_in[1];
    const float* conv_w = (const float*)d_in[2];
    const float* conv_b = (const float*)d_in[3];
    const float* fc_w   = (const float*)d_in[4];
    float* out = (float*)d_out;

    cudaFuncSetAttribute(k_tc, cudaFuncAttributeMaxDynamicSharedMemorySize, SMEM_TOTAL);

    k_prep<<<BB*CIN, 256>>>(deep, conv_w, conv_b, fc_w);
    k_tc  <<<dim3(NN/LT, BB), NTHR, SMEM_TOTAL>>>(x, conv_b, out);
}